// round 11
// baseline (speedup 1.0000x reference)
#include <cuda_runtime.h>
#include <cuda_fp16.h>
#include <mma.h>
#include <cstdint>

using namespace nvcuda;

#define NODES   68000
#define BATCH   4
#define NPROT   17000
#define CDIM    128
#define EMAX    2200000
#define PK      2125      // agg blocks per batch (2125*8 = 17000)
#define NLAYERS 3

#define SCAN_BLOCKS  64
#define SCAN_THREADS 256
#define SCAN_TOTAL   (SCAN_BLOCKS * SCAN_THREADS)
#define SCAN_CHUNK   ((NODES + SCAN_TOTAL - 1) / SCAN_TOTAL)

// ---------------- scratch (allocation-free: __device__ globals) ----------------
__device__ __align__(16) int    g_deg[NODES];
__device__ __align__(16) int    g_ptr[NODES + 1];
__device__ __align__(16) int    g_cursor[NODES];
__device__ __align__(16) int    g_csr[EMAX];
__device__ __align__(16) int    g_tpart[SCAN_TOTAL];
__device__ __align__(16) float  g_dinv[NODES];
__device__ __align__(16) __half g_xh[NODES * 256];     // fp16 copy of x
__device__ __align__(16) __half g_hs[NODES * CDIM];    // hs = dinv * (in @ W), fp16
__device__ __align__(16) __half g_in[NODES * CDIM];    // next-layer input (fp16)
__device__ __align__(16) float  g_ppart[NLAYERS * BATCH * CDIM * PK]; // pool partials
__device__ __align__(16) float  g_pooled[BATCH * CDIM];

// ---------------- fp32 -> fp16 conversion (n multiple of 4) ----------------
__global__ void f2h_kernel(const float* __restrict__ x, __half* __restrict__ xh, int n4) {
    int i = blockIdx.x * blockDim.x + threadIdx.x;
    int stride = gridDim.x * blockDim.x;
    for (int k = i; k < n4; k += stride) {
        float4 v = ((const float4*)x)[k];
        __half2 p0 = __floats2half2_rn(v.x, v.y);
        __half2 p1 = __floats2half2_rn(v.z, v.w);
        uint2 r;
        r.x = *(unsigned int*)&p0;
        r.y = *(unsigned int*)&p1;
        ((uint2*)xh)[k] = r;
    }
}

// ---------------- zero init (deg only) ----------------
__global__ void zero_kernel(int* deg, int n_deg) {
    int i = blockIdx.x * blockDim.x + threadIdx.x;
    int stride = gridDim.x * blockDim.x;
    for (int k = i; k < n_deg; k += stride) deg[k] = 0;
}

__global__ void deg_kernel(const int* __restrict__ dst, int* __restrict__ deg, int E) {
    int i = blockIdx.x * blockDim.x + threadIdx.x;
    if (i < E) atomicAdd(&deg[dst[i]], 1);
}

__global__ void dinv_kernel(const int* __restrict__ deg, float* __restrict__ dinv, int n) {
    int i = blockIdx.x * blockDim.x + threadIdx.x;
    if (i < n) dinv[i] = rsqrtf((float)deg[i] + 1.0f);
}

// ---------------- multi-block scan ----------------
__global__ __launch_bounds__(SCAN_THREADS) void scan_p1_kernel(
    const int* __restrict__ deg, int* __restrict__ tpart)
{
    int t = blockIdx.x * blockDim.x + threadIdx.x;
    int lo = t * SCAN_CHUNK;
    int hi = lo + SCAN_CHUNK; if (hi > NODES) hi = NODES;
    int sum = 0;
    for (int i = lo; i < hi; i++) sum += deg[i];
    tpart[t] = sum;
}

#define P2_T 1024
#define P2_PER (SCAN_TOTAL / P2_T)
__global__ __launch_bounds__(P2_T) void scan_p2_kernel(int* __restrict__ tpart)
{
    __shared__ int bs[P2_T];
    int t = threadIdx.x;
    int v[P2_PER];
    int local = 0;
#pragma unroll
    for (int i = 0; i < P2_PER; i++) {
        v[i] = tpart[t * P2_PER + i];
        local += v[i];
    }
    bs[t] = local;
    __syncthreads();
    for (int off = 1; off < P2_T; off <<= 1) {
        int x = 0;
        if (t >= off) x = bs[t - off];
        __syncthreads();
        if (t >= off) bs[t] += x;
        __syncthreads();
    }
    int run = (t == 0) ? 0 : bs[t - 1];
#pragma unroll
    for (int i = 0; i < P2_PER; i++) {
        tpart[t * P2_PER + i] = run;
        run += v[i];
    }
}

__global__ __launch_bounds__(SCAN_THREADS) void scan_p3_kernel(
    const int* __restrict__ deg, const int* __restrict__ tpart,
    int* __restrict__ ptr, int* __restrict__ cursor, int E)
{
    int t = blockIdx.x * blockDim.x + threadIdx.x;
    int lo = t * SCAN_CHUNK;
    int hi = lo + SCAN_CHUNK; if (hi > NODES) hi = NODES;
    int run = tpart[t];
    for (int i = lo; i < hi; i++) {
        ptr[i] = run;
        cursor[i] = run;
        run += deg[i];
    }
    if (t == 0) ptr[NODES] = E;
}

__global__ void build_csr_kernel(const int* __restrict__ src, const int* __restrict__ dst,
                                 int* __restrict__ cursor, int* __restrict__ csr, int E)
{
    int i = blockIdx.x * blockDim.x + threadIdx.x;
    if (i < E) {
        int d = dst[i];
        int pos = atomicAdd(&cursor[d], 1);
        csr[pos] = src[i];
    }
}

// ---------------- HGEMM (wmma): hs = fp16( dinv * (A @ W) ) ------------------
// A: [M,K] fp16; W: [K,128] fp32 (converted during B-tile smem fill).
#define GBM 128
#define GBK 32
#define LDA 40
#define LDB 136
#define LDC 132
#define SM_AS 0
#define SM_BS (GBM * LDA * 2)
#define SM_CS (SM_BS + GBK * LDB * 2)
#define SM_TOTAL (SM_CS + GBM * LDC * 4)

__global__ __launch_bounds__(256) void hgemm_kernel(
    const __half* __restrict__ A, const float* __restrict__ W,
    const float* __restrict__ dinv, __half* __restrict__ hs, int M, int K)
{
    extern __shared__ char smem[];
    __half* As = (__half*)(smem + SM_AS);
    __half* Bs = (__half*)(smem + SM_BS);
    float*  Cs = (float*)(smem + SM_CS);

    int tx = threadIdx.x;
    int row0 = blockIdx.x * GBM;
    int warp = tx >> 5;
    int wr = warp & 3;
    int wc = warp >> 2;

    wmma::fragment<wmma::accumulator, 16, 16, 16, float> acc[2][4];
#pragma unroll
    for (int mi = 0; mi < 2; mi++)
#pragma unroll
        for (int ni = 0; ni < 4; ni++) wmma::fill_fragment(acc[mi][ni], 0.f);

    for (int k0 = 0; k0 < K; k0 += GBK) {
        // ---- load A tile (fp16) ----
#pragma unroll
        for (int i = tx; i < GBM * GBK / 8; i += 256) {
            int r = i >> 2, c8 = (i & 3) * 8;
            int gr = row0 + r;
            float4 v = make_float4(0.f, 0.f, 0.f, 0.f);
            if (gr < M) v = *(const float4*)&A[(size_t)gr * K + k0 + c8];
            *(float4*)&As[r * LDA + c8] = v;
        }
        // ---- load B tile fp32 -> fp16 ----
#pragma unroll
        for (int i = tx; i < GBK * CDIM / 4; i += 256) {
            int r = i >> 5, c4 = (i & 31) * 4;
            float4 v = *(const float4*)&W[(size_t)(k0 + r) * CDIM + c4];
            __half2 p0 = __floats2half2_rn(v.x, v.y);
            __half2 p1 = __floats2half2_rn(v.z, v.w);
            uint2 w;
            w.x = *(unsigned int*)&p0;
            w.y = *(unsigned int*)&p1;
            *(uint2*)&Bs[r * LDB + c4] = w;
        }
        __syncthreads();
#pragma unroll
        for (int ks = 0; ks < GBK; ks += 16) {
            wmma::fragment<wmma::matrix_a, 16, 16, 16, __half, wmma::row_major> af[2];
            wmma::fragment<wmma::matrix_b, 16, 16, 16, __half, wmma::row_major> bf[4];
#pragma unroll
            for (int mi = 0; mi < 2; mi++)
                wmma::load_matrix_sync(af[mi], &As[(wr * 32 + mi * 16) * LDA + ks], LDA);
#pragma unroll
            for (int ni = 0; ni < 4; ni++)
                wmma::load_matrix_sync(bf[ni], &Bs[ks * LDB + wc * 64 + ni * 16], LDB);
#pragma unroll
            for (int mi = 0; mi < 2; mi++)
#pragma unroll
                for (int ni = 0; ni < 4; ni++)
                    wmma::mma_sync(acc[mi][ni], af[mi], bf[ni], acc[mi][ni]);
        }
        __syncthreads();
    }

#pragma unroll
    for (int mi = 0; mi < 2; mi++)
#pragma unroll
        for (int ni = 0; ni < 4; ni++)
            wmma::store_matrix_sync(&Cs[(wr * 32 + mi * 16) * LDC + wc * 64 + ni * 16],
                                    acc[mi][ni], LDC, wmma::mem_row_major);
    __syncthreads();

    int col4 = (tx & 31) * 4;
    int rstart = tx >> 5;
    for (int r = rstart; r < GBM; r += 8) {
        int gr = row0 + r;
        if (gr < M) {
            float dv = dinv[gr];
            float c0 = Cs[r * LDC + col4 + 0] * dv;
            float c1 = Cs[r * LDC + col4 + 1] * dv;
            float c2 = Cs[r * LDC + col4 + 2] * dv;
            float c3 = Cs[r * LDC + col4 + 3] * dv;
            __half2 p0 = __floats2half2_rn(c0, c1);
            __half2 p1 = __floats2half2_rn(c2, c3);
            uint2 w;
            w.x = *(unsigned int*)&p0;
            w.y = *(unsigned int*)&p1;
            *(uint2*)&hs[(size_t)gr * CDIM + col4] = w;
        }
    }
}

// ---------------- aggregation: warp per dst node + block pool partials -------
// Edge loop: scalar prologue to 4-aligned csr offset, then int4 index loads
// (LDG.128 broadcast) with 8-edge batched row gathers for deep MLP.
__global__ __launch_bounds__(256) void agg_kernel(
    const int* __restrict__ ptr, const int* __restrict__ csr,
    const float* __restrict__ dinv, const __half* __restrict__ hs,
    const float* __restrict__ bias, const int* __restrict__ mask,
    __half* __restrict__ nxt, float* __restrict__ ppart,
    int write_nxt, int layer)
{
    __shared__ float pbuf[8][CDIM];
    int tx = threadIdx.x;
    int lane = tx & 31;
    int warp = tx >> 5;
    int b = blockIdx.y;
    int node = b * NPROT + blockIdx.x * 8 + warp;

    int beg = __ldg(&ptr[node]);
    int end = __ldg(&ptr[node + 1]);
    int co = lane * 4;

    float a0, a1, a2, a3;
    {
        uint2 r = *(const uint2*)(hs + (size_t)node * CDIM + co);
        float2 f0 = __half22float2(*(__half2*)&r.x);
        float2 f1 = __half22float2(*(__half2*)&r.y);
        a0 = f0.x; a1 = f0.y; a2 = f1.x; a3 = f1.y;
    }

    int e = beg;
    // scalar prologue up to 4-aligned offset
    int lim = (beg + 3) & ~3;
    if (lim > end) lim = end;
    for (; e < lim; e++) {
        int si = __ldg(&csr[e]);
        uint2 r = *(const uint2*)(hs + (size_t)si * CDIM + co);
        float2 f;
        f = __half22float2(*(__half2*)&r.x); a0 += f.x; a1 += f.y;
        f = __half22float2(*(__half2*)&r.y); a2 += f.x; a3 += f.y;
    }
    // 8-edge batches: two int4 index loads + 8 row loads issued before use
    for (; e + 8 <= end; e += 8) {
        int4 i0 = *(const int4*)&csr[e];
        int4 i1 = *(const int4*)&csr[e + 4];
        uint2 r0 = *(const uint2*)(hs + (size_t)i0.x * CDIM + co);
        uint2 r1 = *(const uint2*)(hs + (size_t)i0.y * CDIM + co);
        uint2 r2 = *(const uint2*)(hs + (size_t)i0.z * CDIM + co);
        uint2 r3 = *(const uint2*)(hs + (size_t)i0.w * CDIM + co);
        uint2 r4 = *(const uint2*)(hs + (size_t)i1.x * CDIM + co);
        uint2 r5 = *(const uint2*)(hs + (size_t)i1.y * CDIM + co);
        uint2 r6 = *(const uint2*)(hs + (size_t)i1.z * CDIM + co);
        uint2 r7 = *(const uint2*)(hs + (size_t)i1.w * CDIM + co);
        float2 f;
        f = __half22float2(*(__half2*)&r0.x); a0 += f.x; a1 += f.y;
        f = __half22float2(*(__half2*)&r0.y); a2 += f.x; a3 += f.y;
        f = __half22float2(*(__half2*)&r1.x); a0 += f.x; a1 += f.y;
        f = __half22float2(*(__half2*)&r1.y); a2 += f.x; a3 += f.y;
        f = __half22float2(*(__half2*)&r2.x); a0 += f.x; a1 += f.y;
        f = __half22float2(*(__half2*)&r2.y); a2 += f.x; a3 += f.y;
        f = __half22float2(*(__half2*)&r3.x); a0 += f.x; a1 += f.y;
        f = __half22float2(*(__half2*)&r3.y); a2 += f.x; a3 += f.y;
        f = __half22float2(*(__half2*)&r4.x); a0 += f.x; a1 += f.y;
        f = __half22float2(*(__half2*)&r4.y); a2 += f.x; a3 += f.y;
        f = __half22float2(*(__half2*)&r5.x); a0 += f.x; a1 += f.y;
        f = __half22float2(*(__half2*)&r5.y); a2 += f.x; a3 += f.y;
        f = __half22float2(*(__half2*)&r6.x); a0 += f.x; a1 += f.y;
        f = __half22float2(*(__half2*)&r6.y); a2 += f.x; a3 += f.y;
        f = __half22float2(*(__half2*)&r7.x); a0 += f.x; a1 += f.y;
        f = __half22float2(*(__half2*)&r7.y); a2 += f.x; a3 += f.y;
    }
    // 4-edge batch
    for (; e + 4 <= end; e += 4) {
        int4 i0 = *(const int4*)&csr[e];
        uint2 r0 = *(const uint2*)(hs + (size_t)i0.x * CDIM + co);
        uint2 r1 = *(const uint2*)(hs + (size_t)i0.y * CDIM + co);
        uint2 r2 = *(const uint2*)(hs + (size_t)i0.z * CDIM + co);
        uint2 r3 = *(const uint2*)(hs + (size_t)i0.w * CDIM + co);
        float2 f;
        f = __half22float2(*(__half2*)&r0.x); a0 += f.x; a1 += f.y;
        f = __half22float2(*(__half2*)&r0.y); a2 += f.x; a3 += f.y;
        f = __half22float2(*(__half2*)&r1.x); a0 += f.x; a1 += f.y;
        f = __half22float2(*(__half2*)&r1.y); a2 += f.x; a3 += f.y;
        f = __half22float2(*(__half2*)&r2.x); a0 += f.x; a1 += f.y;
        f = __half22float2(*(__half2*)&r2.y); a2 += f.x; a3 += f.y;
        f = __half22float2(*(__half2*)&r3.x); a0 += f.x; a1 += f.y;
        f = __half22float2(*(__half2*)&r3.y); a2 += f.x; a3 += f.y;
    }
    // scalar tail
    for (; e < end; e++) {
        int si = __ldg(&csr[e]);
        uint2 r = *(const uint2*)(hs + (size_t)si * CDIM + co);
        float2 f;
        f = __half22float2(*(__half2*)&r.x); a0 += f.x; a1 += f.y;
        f = __half22float2(*(__half2*)&r.y); a2 += f.x; a3 += f.y;
    }

    float dv = dinv[node];
    float4 b4 = *(const float4*)&bias[co];
    float r0 = fmaxf(a0 * dv + b4.x, 0.f);
    float r1 = fmaxf(a1 * dv + b4.y, 0.f);
    float r2 = fmaxf(a2 * dv + b4.z, 0.f);
    float r3 = fmaxf(a3 * dv + b4.w, 0.f);

    if (write_nxt) {
        __half2 p0 = __floats2half2_rn(r0, r1);
        __half2 p1 = __floats2half2_rn(r2, r3);
        uint2 w;
        w.x = *(unsigned int*)&p0;
        w.y = *(unsigned int*)&p1;
        *(uint2*)&nxt[(size_t)node * CDIM + co] = w;
    }

    float mf = __ldg(&mask[node]) ? 1.f : 0.f;
    pbuf[warp][co + 0] = r0 * mf;
    pbuf[warp][co + 1] = r1 * mf;
    pbuf[warp][co + 2] = r2 * mf;
    pbuf[warp][co + 3] = r3 * mf;
    __syncthreads();

    if (tx < CDIM) {
        float sum = 0.f;
#pragma unroll
        for (int w = 0; w < 8; w++) sum += pbuf[w][tx];
        ppart[(((size_t)layer * BATCH + b) * CDIM + tx) * PK + blockIdx.x] = sum;
    }
}

// ---------------- pool reduce ----------------
__global__ __launch_bounds__(256) void pool_reduce_kernel(
    const float* __restrict__ ppart, float* __restrict__ pooled)
{
    __shared__ float red[256];
    int bc = blockIdx.x;
    int tx = threadIdx.x;
    float sum = 0.f;
#pragma unroll
    for (int l = 0; l < NLAYERS; l++) {
        const float* row = ppart + (((size_t)l * BATCH) * CDIM + bc) * PK;
        for (int k = tx; k < PK; k += 256) sum += row[k];
    }
    red[tx] = sum;
    __syncthreads();
    for (int off = 128; off > 0; off >>= 1) {
        if (tx < off) red[tx] += red[tx + off];
        __syncthreads();
    }
    if (tx == 0) pooled[bc] = red[0];
}

// ---------------- tiny MLP ----------------
__global__ __launch_bounds__(256) void mlp_kernel(
    const float* __restrict__ pooled,
    const float* __restrict__ lw1, const float* __restrict__ lb1,
    const float* __restrict__ lw2, const float* __restrict__ lb2,
    const float* __restrict__ lw3, const float* __restrict__ lb3,
    const float* __restrict__ lw4, const float* __restrict__ lb4,
    float* __restrict__ out)
{
    __shared__ float sp[BATCH * 128];
    __shared__ float z1[BATCH * 256];
    __shared__ float z2[BATCH * 64];
    __shared__ float z3[BATCH * 16];
    int tx = threadIdx.x;

    for (int i = tx; i < BATCH * 128; i += 256) sp[i] = pooled[i];
    __syncthreads();

    for (int i = tx; i < BATCH * 256; i += 256) {
        int b = i >> 8, c = i & 255;
        float acc = lb1[c];
        for (int k = 0; k < 128; k++) acc += sp[b * 128 + k] * lw1[k * 256 + c];
        z1[i] = fmaxf(acc, 0.f);
    }
    __syncthreads();

    for (int i = tx; i < BATCH * 64; i += 256) {
        int b = i >> 6, c = i & 63;
        float acc = lb2[c];
        for (int k = 0; k < 256; k++) acc += z1[b * 256 + k] * lw2[k * 64 + c];
        z2[i] = fmaxf(acc, 0.f);
    }
    __syncthreads();

    if (tx < BATCH * 16) {
        int b = tx >> 4, c = tx & 15;
        float acc = lb3[c];
        for (int k = 0; k < 64; k++) acc += z2[b * 64 + k] * lw3[k * 16 + c];
        z3[tx] = fmaxf(acc, 0.f);
    }
    __syncthreads();

    if (tx < BATCH) {
        float acc = lb4[0];
        for (int k = 0; k < 16; k++) acc += z3[tx * 16 + k] * lw4[k];
        out[tx] = acc;
    }
}

// ---------------- launch ----------------
extern "C" void kernel_launch(void* const* d_in, const int* in_sizes, int n_in,
                              void* d_out, int out_size)
{
    const float* x    = (const float*)d_in[0];
    const int*   eidx = (const int*)d_in[1];
    const int*   mask = (const int*)d_in[2];
    const float* W1 = (const float*)d_in[3];  const float* b1 = (const float*)d_in[4];
    const float* W2 = (const float*)d_in[5];  const float* b2 = (const float*)d_in[6];
    const float* W3 = (const float*)d_in[7];  const float* b3 = (const float*)d_in[8];
    const float* lw1 = (const float*)d_in[9];  const float* lb1 = (const float*)d_in[10];
    const float* lw2 = (const float*)d_in[11]; const float* lb2 = (const float*)d_in[12];
    const float* lw3 = (const float*)d_in[13]; const float* lb3 = (const float*)d_in[14];
    const float* lw4 = (const float*)d_in[15]; const float* lb4 = (const float*)d_in[16];
    float* out = (float*)d_out;

    int M = NODES;
    int E = in_sizes[1] / 2;
    const int* src = eidx;
    const int* dst = eidx + E;

    void *p_deg, *p_ptr, *p_cur, *p_csr, *p_tp, *p_dinv, *p_xh, *p_hs, *p_in, *p_pp, *p_pool;
    cudaGetSymbolAddress(&p_deg, g_deg);
    cudaGetSymbolAddress(&p_ptr, g_ptr);
    cudaGetSymbolAddress(&p_cur, g_cursor);
    cudaGetSymbolAddress(&p_csr, g_csr);
    cudaGetSymbolAddress(&p_tp, g_tpart);
    cudaGetSymbolAddress(&p_dinv, g_dinv);
    cudaGetSymbolAddress(&p_xh, g_xh);
    cudaGetSymbolAddress(&p_hs, g_hs);
    cudaGetSymbolAddress(&p_in, g_in);
    cudaGetSymbolAddress(&p_pp, g_ppart);
    cudaGetSymbolAddress(&p_pool, g_pooled);
    int*    deg  = (int*)p_deg;
    int*    ptr  = (int*)p_ptr;
    int*    cur  = (int*)p_cur;
    int*    csr  = (int*)p_csr;
    int*    tp   = (int*)p_tp;
    float*  dinv = (float*)p_dinv;
    __half* xh   = (__half*)p_xh;
    __half* hs   = (__half*)p_hs;
    __half* in   = (__half*)p_in;
    float*  pp   = (float*)p_pp;
    float*  pool = (float*)p_pool;

    cudaFuncSetAttribute(hgemm_kernel, cudaFuncAttributeMaxDynamicSharedMemorySize, SM_TOTAL);

    dim3 agg_grid(PK, BATCH);
    int gemm_blocks = (M + GBM - 1) / GBM;

    // x conversion (independent; runs while nothing else is queued)
    f2h_kernel<<<1024, 256>>>(x, xh, M * 256 / 4);

    // graph preprocessing
    zero_kernel<<<256, 256>>>(deg, M);
    deg_kernel<<<(E + 255) / 256, 256>>>(dst, deg, E);
    dinv_kernel<<<(M + 255) / 256, 256>>>(deg, dinv, M);

    // layer-1 GEMM only needs xh + dinv — launch before the CSR chain
    hgemm_kernel<<<gemm_blocks, 256, SM_TOTAL>>>(xh, W1, dinv, hs, M, 256);

    scan_p1_kernel<<<SCAN_BLOCKS, SCAN_THREADS>>>(deg, tp);
    scan_p2_kernel<<<1, P2_T>>>(tp);
    scan_p3_kernel<<<SCAN_BLOCKS, SCAN_THREADS>>>(deg, tp, ptr, cur, E);
    build_csr_kernel<<<(E + 255) / 256, 256>>>(src, dst, cur, csr, E);

    // layer 1 aggregation
    agg_kernel<<<agg_grid, 256>>>(ptr, csr, dinv, hs, b1, mask, in, pp, 1, 0);

    // layer 2
    hgemm_kernel<<<gemm_blocks, 256, SM_TOTAL>>>(in, W2, dinv, hs, M, 128);
    agg_kernel<<<agg_grid, 256>>>(ptr, csr, dinv, hs, b2, mask, in, pp, 1, 1);

    // layer 3 — no next-layer input needed
    hgemm_kernel<<<gemm_blocks, 256, SM_TOTAL>>>(in, W3, dinv, hs, M, 128);
    agg_kernel<<<agg_grid, 256>>>(ptr, csr, dinv, hs, b3, mask, in, pp, 0, 2);

    // pool reduce (no atomics)
    pool_reduce_kernel<<<BATCH * CDIM, 256>>>(pp, pool);

    // MLP head
    mlp_kernel<<<1, 256>>>(pool, lw1, lb1, lw2, lb2, lw3, lb3, lw4, lb4, out);
}

// round 12
// speedup vs baseline: 1.3922x; 1.3922x over previous
#include <cuda_runtime.h>
#include <cuda_fp16.h>
#include <mma.h>
#include <cstdint>

using namespace nvcuda;

#define NODES   68000
#define BATCH   4
#define NPROT   17000
#define CDIM    128
#define EMAX    2200000
#define PK      2125      // agg blocks per batch (2125*8 = 17000)
#define NLAYERS 3

#define SCAN_BLOCKS  64
#define SCAN_THREADS 256
#define SCAN_TOTAL   (SCAN_BLOCKS * SCAN_THREADS)
#define SCAN_CHUNK   ((NODES + SCAN_TOTAL - 1) / SCAN_TOTAL)

// ---------------- scratch (allocation-free: __device__ globals) ----------------
__device__ __align__(16) int    g_deg[NODES];
__device__ __align__(16) int    g_ptr[NODES + 1];
__device__ __align__(16) int    g_cursor[NODES];
__device__ __align__(16) int    g_csr[EMAX];
__device__ __align__(16) int    g_tpart[SCAN_TOTAL];
__device__ __align__(16) float  g_dinv[NODES];
__device__ __align__(16) __half g_xh[NODES * 256];     // fp16 copy of x
__device__ __align__(16) __half g_hs[NODES * CDIM];    // hs = dinv * (in @ W), fp16
__device__ __align__(16) __half g_in[NODES * CDIM];    // next-layer input (fp16)
__device__ __align__(16) float  g_ppart[NLAYERS * BATCH * CDIM * PK]; // pool partials
__device__ __align__(16) float  g_pooled[BATCH * CDIM];

// ---------------- fp32 -> fp16 conversion (n multiple of 4) ----------------
__global__ void f2h_kernel(const float* __restrict__ x, __half* __restrict__ xh, int n4) {
    int i = blockIdx.x * blockDim.x + threadIdx.x;
    int stride = gridDim.x * blockDim.x;
    for (int k = i; k < n4; k += stride) {
        float4 v = ((const float4*)x)[k];
        __half2 p0 = __floats2half2_rn(v.x, v.y);
        __half2 p1 = __floats2half2_rn(v.z, v.w);
        uint2 r;
        r.x = *(unsigned int*)&p0;
        r.y = *(unsigned int*)&p1;
        ((uint2*)xh)[k] = r;
    }
}

// ---------------- zero init (deg only) ----------------
__global__ void zero_kernel(int* deg, int n_deg) {
    int i = blockIdx.x * blockDim.x + threadIdx.x;
    int stride = gridDim.x * blockDim.x;
    for (int k = i; k < n_deg; k += stride) deg[k] = 0;
}

__global__ void deg_kernel(const int* __restrict__ dst, int* __restrict__ deg, int E) {
    int i = blockIdx.x * blockDim.x + threadIdx.x;
    if (i < E) atomicAdd(&deg[dst[i]], 1);
}

__global__ void dinv_kernel(const int* __restrict__ deg, float* __restrict__ dinv, int n) {
    int i = blockIdx.x * blockDim.x + threadIdx.x;
    if (i < n) dinv[i] = rsqrtf((float)deg[i] + 1.0f);
}

// ---------------- multi-block scan ----------------
__global__ __launch_bounds__(SCAN_THREADS) void scan_p1_kernel(
    const int* __restrict__ deg, int* __restrict__ tpart)
{
    int t = blockIdx.x * blockDim.x + threadIdx.x;
    int lo = t * SCAN_CHUNK;
    int hi = lo + SCAN_CHUNK; if (hi > NODES) hi = NODES;
    int sum = 0;
    for (int i = lo; i < hi; i++) sum += deg[i];
    tpart[t] = sum;
}

#define P2_T 1024
#define P2_PER (SCAN_TOTAL / P2_T)
__global__ __launch_bounds__(P2_T) void scan_p2_kernel(int* __restrict__ tpart)
{
    __shared__ int bs[P2_T];
    int t = threadIdx.x;
    int v[P2_PER];
    int local = 0;
#pragma unroll
    for (int i = 0; i < P2_PER; i++) {
        v[i] = tpart[t * P2_PER + i];
        local += v[i];
    }
    bs[t] = local;
    __syncthreads();
    for (int off = 1; off < P2_T; off <<= 1) {
        int x = 0;
        if (t >= off) x = bs[t - off];
        __syncthreads();
        if (t >= off) bs[t] += x;
        __syncthreads();
    }
    int run = (t == 0) ? 0 : bs[t - 1];
#pragma unroll
    for (int i = 0; i < P2_PER; i++) {
        tpart[t * P2_PER + i] = run;
        run += v[i];
    }
}

__global__ __launch_bounds__(SCAN_THREADS) void scan_p3_kernel(
    const int* __restrict__ deg, const int* __restrict__ tpart,
    int* __restrict__ ptr, int* __restrict__ cursor, int E)
{
    int t = blockIdx.x * blockDim.x + threadIdx.x;
    int lo = t * SCAN_CHUNK;
    int hi = lo + SCAN_CHUNK; if (hi > NODES) hi = NODES;
    int run = tpart[t];
    for (int i = lo; i < hi; i++) {
        ptr[i] = run;
        cursor[i] = run;
        run += deg[i];
    }
    if (t == 0) ptr[NODES] = E;
}

__global__ void build_csr_kernel(const int* __restrict__ src, const int* __restrict__ dst,
                                 int* __restrict__ cursor, int* __restrict__ csr, int E)
{
    int i = blockIdx.x * blockDim.x + threadIdx.x;
    if (i < E) {
        int d = dst[i];
        int pos = atomicAdd(&cursor[d], 1);
        csr[pos] = src[i];
    }
}

// ---------------- HGEMM (wmma): hs = fp16( dinv * (A @ W) ) ------------------
// A: [M,K] fp16; W: [K,128] fp32 (converted during B-tile smem fill).
#define GBM 128
#define GBK 32
#define LDA 40
#define LDB 136
#define LDC 132
#define SM_AS 0
#define SM_BS (GBM * LDA * 2)
#define SM_CS (SM_BS + GBK * LDB * 2)
#define SM_TOTAL (SM_CS + GBM * LDC * 4)

__global__ __launch_bounds__(256) void hgemm_kernel(
    const __half* __restrict__ A, const float* __restrict__ W,
    const float* __restrict__ dinv, __half* __restrict__ hs, int M, int K)
{
    extern __shared__ char smem[];
    __half* As = (__half*)(smem + SM_AS);
    __half* Bs = (__half*)(smem + SM_BS);
    float*  Cs = (float*)(smem + SM_CS);

    int tx = threadIdx.x;
    int row0 = blockIdx.x * GBM;
    int warp = tx >> 5;
    int wr = warp & 3;
    int wc = warp >> 2;

    wmma::fragment<wmma::accumulator, 16, 16, 16, float> acc[2][4];
#pragma unroll
    for (int mi = 0; mi < 2; mi++)
#pragma unroll
        for (int ni = 0; ni < 4; ni++) wmma::fill_fragment(acc[mi][ni], 0.f);

    for (int k0 = 0; k0 < K; k0 += GBK) {
        // ---- load A tile (fp16) ----
#pragma unroll
        for (int i = tx; i < GBM * GBK / 8; i += 256) {
            int r = i >> 2, c8 = (i & 3) * 8;
            int gr = row0 + r;
            float4 v = make_float4(0.f, 0.f, 0.f, 0.f);
            if (gr < M) v = *(const float4*)&A[(size_t)gr * K + k0 + c8];
            *(float4*)&As[r * LDA + c8] = v;
        }
        // ---- load B tile fp32 -> fp16 ----
#pragma unroll
        for (int i = tx; i < GBK * CDIM / 4; i += 256) {
            int r = i >> 5, c4 = (i & 31) * 4;
            float4 v = *(const float4*)&W[(size_t)(k0 + r) * CDIM + c4];
            __half2 p0 = __floats2half2_rn(v.x, v.y);
            __half2 p1 = __floats2half2_rn(v.z, v.w);
            uint2 w;
            w.x = *(unsigned int*)&p0;
            w.y = *(unsigned int*)&p1;
            *(uint2*)&Bs[r * LDB + c4] = w;
        }
        __syncthreads();
#pragma unroll
        for (int ks = 0; ks < GBK; ks += 16) {
            wmma::fragment<wmma::matrix_a, 16, 16, 16, __half, wmma::row_major> af[2];
            wmma::fragment<wmma::matrix_b, 16, 16, 16, __half, wmma::row_major> bf[4];
#pragma unroll
            for (int mi = 0; mi < 2; mi++)
                wmma::load_matrix_sync(af[mi], &As[(wr * 32 + mi * 16) * LDA + ks], LDA);
#pragma unroll
            for (int ni = 0; ni < 4; ni++)
                wmma::load_matrix_sync(bf[ni], &Bs[ks * LDB + wc * 64 + ni * 16], LDB);
#pragma unroll
            for (int mi = 0; mi < 2; mi++)
#pragma unroll
                for (int ni = 0; ni < 4; ni++)
                    wmma::mma_sync(acc[mi][ni], af[mi], bf[ni], acc[mi][ni]);
        }
        __syncthreads();
    }

#pragma unroll
    for (int mi = 0; mi < 2; mi++)
#pragma unroll
        for (int ni = 0; ni < 4; ni++)
            wmma::store_matrix_sync(&Cs[(wr * 32 + mi * 16) * LDC + wc * 64 + ni * 16],
                                    acc[mi][ni], LDC, wmma::mem_row_major);
    __syncthreads();

    int col4 = (tx & 31) * 4;
    int rstart = tx >> 5;
    for (int r = rstart; r < GBM; r += 8) {
        int gr = row0 + r;
        if (gr < M) {
            float dv = dinv[gr];
            float c0 = Cs[r * LDC + col4 + 0] * dv;
            float c1 = Cs[r * LDC + col4 + 1] * dv;
            float c2 = Cs[r * LDC + col4 + 2] * dv;
            float c3 = Cs[r * LDC + col4 + 3] * dv;
            __half2 p0 = __floats2half2_rn(c0, c1);
            __half2 p1 = __floats2half2_rn(c2, c3);
            uint2 w;
            w.x = *(unsigned int*)&p0;
            w.y = *(unsigned int*)&p1;
            *(uint2*)&hs[(size_t)gr * CDIM + col4] = w;
        }
    }
}

// ---------------- aggregation: warp per dst node, 2 rows per LDG -------------
// Half-warps: lanes 0-15 handle even edges, 16-31 odd edges; each lane loads
// uint4 (8 halves = 16B), so one warp LDG covers 2 full 256B rows. MLP depth
// per warp stays ~4 outstanding rows (same as the proven 329.8us kernel).
__global__ __launch_bounds__(256) void agg_kernel(
    const int* __restrict__ ptr, const int* __restrict__ csr,
    const float* __restrict__ dinv, const __half* __restrict__ hs,
    const float* __restrict__ bias, const int* __restrict__ mask,
    __half* __restrict__ nxt, float* __restrict__ ppart,
    int write_nxt, int layer)
{
    __shared__ float pbuf[8][CDIM];
    int tx = threadIdx.x;
    int lane = tx & 31;
    int warp = tx >> 5;
    int hl = lane >> 4;          // half-warp index (0: even edges, 1: odd)
    int li = lane & 15;
    int co = li * 8;             // 8 halves (16B) per lane
    int b = blockIdx.y;
    int node = b * NPROT + blockIdx.x * 8 + warp;

    int beg = __ldg(&ptr[node]);
    int end = __ldg(&ptr[node + 1]);

    float a0 = 0.f, a1 = 0.f, a2 = 0.f, a3 = 0.f;
    float a4 = 0.f, a5 = 0.f, a6 = 0.f, a7 = 0.f;

#define ACC_ROW(R)  do {                                              \
        float2 f;                                                     \
        f = __half22float2(*(__half2*)&(R).x); a0 += f.x; a1 += f.y;  \
        f = __half22float2(((__half2*)&(R).x)[1]); a2 += f.x; a3 += f.y; \
        f = __half22float2(*(__half2*)&(R).z); a4 += f.x; a5 += f.y;  \
        f = __half22float2(((__half2*)&(R).z)[1]); a6 += f.x; a7 += f.y; \
    } while (0)

    // self term: only half 0 accumulates (counted once after combine)
    if (hl == 0) {
        uint4 r = *(const uint4*)(hs + (size_t)node * CDIM + co);
        ACC_ROW(r);
    }

    int e = beg;
    // 8 edges per iteration = 4 pair-loads per half-warp (MLP ~4 rows/warp)
    for (; e + 8 <= end; e += 8) {
        int i0 = __ldg(&csr[e + 0 + hl]);
        int i1 = __ldg(&csr[e + 2 + hl]);
        int i2 = __ldg(&csr[e + 4 + hl]);
        int i3 = __ldg(&csr[e + 6 + hl]);
        uint4 r0 = *(const uint4*)(hs + (size_t)i0 * CDIM + co);
        uint4 r1 = *(const uint4*)(hs + (size_t)i1 * CDIM + co);
        uint4 r2 = *(const uint4*)(hs + (size_t)i2 * CDIM + co);
        uint4 r3 = *(const uint4*)(hs + (size_t)i3 * CDIM + co);
        ACC_ROW(r0);
        ACC_ROW(r1);
        ACC_ROW(r2);
        ACC_ROW(r3);
    }
    // pair tail
    for (; e < end; e += 2) {
        if (e + hl < end) {
            int si = __ldg(&csr[e + hl]);
            uint4 r = *(const uint4*)(hs + (size_t)si * CDIM + co);
            ACC_ROW(r);
        }
    }
#undef ACC_ROW

    // combine the two half-warps (lane i += lane i+16)
    a0 += __shfl_down_sync(0xffffffffu, a0, 16);
    a1 += __shfl_down_sync(0xffffffffu, a1, 16);
    a2 += __shfl_down_sync(0xffffffffu, a2, 16);
    a3 += __shfl_down_sync(0xffffffffu, a3, 16);
    a4 += __shfl_down_sync(0xffffffffu, a4, 16);
    a5 += __shfl_down_sync(0xffffffffu, a5, 16);
    a6 += __shfl_down_sync(0xffffffffu, a6, 16);
    a7 += __shfl_down_sync(0xffffffffu, a7, 16);

    if (hl == 0) {
        float dv = dinv[node];
        float4 bA = *(const float4*)&bias[co];
        float4 bB = *(const float4*)&bias[co + 4];
        float r0 = fmaxf(a0 * dv + bA.x, 0.f);
        float r1 = fmaxf(a1 * dv + bA.y, 0.f);
        float r2 = fmaxf(a2 * dv + bA.z, 0.f);
        float r3 = fmaxf(a3 * dv + bA.w, 0.f);
        float r4 = fmaxf(a4 * dv + bB.x, 0.f);
        float r5 = fmaxf(a5 * dv + bB.y, 0.f);
        float r6 = fmaxf(a6 * dv + bB.z, 0.f);
        float r7 = fmaxf(a7 * dv + bB.w, 0.f);

        if (write_nxt) {
            __half2 p0 = __floats2half2_rn(r0, r1);
            __half2 p1 = __floats2half2_rn(r2, r3);
            __half2 p2 = __floats2half2_rn(r4, r5);
            __half2 p3 = __floats2half2_rn(r6, r7);
            uint4 w;
            w.x = *(unsigned int*)&p0;
            w.y = *(unsigned int*)&p1;
            w.z = *(unsigned int*)&p2;
            w.w = *(unsigned int*)&p3;
            *(uint4*)&nxt[(size_t)node * CDIM + co] = w;
        }

        float mf = __ldg(&mask[node]) ? 1.f : 0.f;
        float4 qa = make_float4(r0 * mf, r1 * mf, r2 * mf, r3 * mf);
        float4 qb = make_float4(r4 * mf, r5 * mf, r6 * mf, r7 * mf);
        *(float4*)&pbuf[warp][co] = qa;
        *(float4*)&pbuf[warp][co + 4] = qb;
    }
    __syncthreads();

    if (tx < CDIM) {
        float sum = 0.f;
#pragma unroll
        for (int w = 0; w < 8; w++) sum += pbuf[w][tx];
        ppart[(((size_t)layer * BATCH + b) * CDIM + tx) * PK + blockIdx.x] = sum;
    }
}

// ---------------- pool reduce ----------------
__global__ __launch_bounds__(256) void pool_reduce_kernel(
    const float* __restrict__ ppart, float* __restrict__ pooled)
{
    __shared__ float red[256];
    int bc = blockIdx.x;
    int tx = threadIdx.x;
    float sum = 0.f;
#pragma unroll
    for (int l = 0; l < NLAYERS; l++) {
        const float* row = ppart + (((size_t)l * BATCH) * CDIM + bc) * PK;
        for (int k = tx; k < PK; k += 256) sum += row[k];
    }
    red[tx] = sum;
    __syncthreads();
    for (int off = 128; off > 0; off >>= 1) {
        if (tx < off) red[tx] += red[tx + off];
        __syncthreads();
    }
    if (tx == 0) pooled[bc] = red[0];
}

// ---------------- tiny MLP ----------------
__global__ __launch_bounds__(256) void mlp_kernel(
    const float* __restrict__ pooled,
    const float* __restrict__ lw1, const float* __restrict__ lb1,
    const float* __restrict__ lw2, const float* __restrict__ lb2,
    const float* __restrict__ lw3, const float* __restrict__ lb3,
    const float* __restrict__ lw4, const float* __restrict__ lb4,
    float* __restrict__ out)
{
    __shared__ float sp[BATCH * 128];
    __shared__ float z1[BATCH * 256];
    __shared__ float z2[BATCH * 64];
    __shared__ float z3[BATCH * 16];
    int tx = threadIdx.x;

    for (int i = tx; i < BATCH * 128; i += 256) sp[i] = pooled[i];
    __syncthreads();

    for (int i = tx; i < BATCH * 256; i += 256) {
        int b = i >> 8, c = i & 255;
        float acc = lb1[c];
        for (int k = 0; k < 128; k++) acc += sp[b * 128 + k] * lw1[k * 256 + c];
        z1[i] = fmaxf(acc, 0.f);
    }
    __syncthreads();

    for (int i = tx; i < BATCH * 64; i += 256) {
        int b = i >> 6, c = i & 63;
        float acc = lb2[c];
        for (int k = 0; k < 256; k++) acc += z1[b * 256 + k] * lw2[k * 64 + c];
        z2[i] = fmaxf(acc, 0.f);
    }
    __syncthreads();

    if (tx < BATCH * 16) {
        int b = tx >> 4, c = tx & 15;
        float acc = lb3[c];
        for (int k = 0; k < 64; k++) acc += z2[b * 64 + k] * lw3[k * 16 + c];
        z3[tx] = fmaxf(acc, 0.f);
    }
    __syncthreads();

    if (tx < BATCH) {
        float acc = lb4[0];
        for (int k = 0; k < 16; k++) acc += z3[tx * 16 + k] * lw4[k];
        out[tx] = acc;
    }
}

// ---------------- launch ----------------
extern "C" void kernel_launch(void* const* d_in, const int* in_sizes, int n_in,
                              void* d_out, int out_size)
{
    const float* x    = (const float*)d_in[0];
    const int*   eidx = (const int*)d_in[1];
    const int*   mask = (const int*)d_in[2];
    const float* W1 = (const float*)d_in[3];  const float* b1 = (const float*)d_in[4];
    const float* W2 = (const float*)d_in[5];  const float* b2 = (const float*)d_in[6];
    const float* W3 = (const float*)d_in[7];  const float* b3 = (const float*)d_in[8];
    const float* lw1 = (const float*)d_in[9];  const float* lb1 = (const float*)d_in[10];
    const float* lw2 = (const float*)d_in[11]; const float* lb2 = (const float*)d_in[12];
    const float* lw3 = (const float*)d_in[13]; const float* lb3 = (const float*)d_in[14];
    const float* lw4 = (const float*)d_in[15]; const float* lb4 = (const float*)d_in[16];
    float* out = (float*)d_out;

    int M = NODES;
    int E = in_sizes[1] / 2;
    const int* src = eidx;
    const int* dst = eidx + E;

    void *p_deg, *p_ptr, *p_cur, *p_csr, *p_tp, *p_dinv, *p_xh, *p_hs, *p_in, *p_pp, *p_pool;
    cudaGetSymbolAddress(&p_deg, g_deg);
    cudaGetSymbolAddress(&p_ptr, g_ptr);
    cudaGetSymbolAddress(&p_cur, g_cursor);
    cudaGetSymbolAddress(&p_csr, g_csr);
    cudaGetSymbolAddress(&p_tp, g_tpart);
    cudaGetSymbolAddress(&p_dinv, g_dinv);
    cudaGetSymbolAddress(&p_xh, g_xh);
    cudaGetSymbolAddress(&p_hs, g_hs);
    cudaGetSymbolAddress(&p_in, g_in);
    cudaGetSymbolAddress(&p_pp, g_ppart);
    cudaGetSymbolAddress(&p_pool, g_pooled);
    int*    deg  = (int*)p_deg;
    int*    ptr  = (int*)p_ptr;
    int*    cur  = (int*)p_cur;
    int*    csr  = (int*)p_csr;
    int*    tp   = (int*)p_tp;
    float*  dinv = (float*)p_dinv;
    __half* xh   = (__half*)p_xh;
    __half* hs   = (__half*)p_hs;
    __half* in   = (__half*)p_in;
    float*  pp   = (float*)p_pp;
    float*  pool = (float*)p_pool;

    cudaFuncSetAttribute(hgemm_kernel, cudaFuncAttributeMaxDynamicSharedMemorySize, SM_TOTAL);

    dim3 agg_grid(PK, BATCH);
    int gemm_blocks = (M + GBM - 1) / GBM;

    // x conversion (independent; runs while nothing else is queued)
    f2h_kernel<<<1024, 256>>>(x, xh, M * 256 / 4);

    // graph preprocessing
    zero_kernel<<<256, 256>>>(deg, M);
    deg_kernel<<<(E + 255) / 256, 256>>>(dst, deg, E);
    dinv_kernel<<<(M + 255) / 256, 256>>>(deg, dinv, M);

    // layer-1 GEMM only needs xh + dinv — launch before the CSR chain
    hgemm_kernel<<<gemm_blocks, 256, SM_TOTAL>>>(xh, W1, dinv, hs, M, 256);

    scan_p1_kernel<<<SCAN_BLOCKS, SCAN_THREADS>>>(deg, tp);
    scan_p2_kernel<<<1, P2_T>>>(tp);
    scan_p3_kernel<<<SCAN_BLOCKS, SCAN_THREADS>>>(deg, tp, ptr, cur, E);
    build_csr_kernel<<<(E + 255) / 256, 256>>>(src, dst, cur, csr, E);

    // layer 1 aggregation
    agg_kernel<<<agg_grid, 256>>>(ptr, csr, dinv, hs, b1, mask, in, pp, 1, 0);

    // layer 2
    hgemm_kernel<<<gemm_blocks, 256, SM_TOTAL>>>(in, W2, dinv, hs, M, 128);
    agg_kernel<<<agg_grid, 256>>>(ptr, csr, dinv, hs, b2, mask, in, pp, 1, 1);

    // layer 3 — no next-layer input needed
    hgemm_kernel<<<gemm_blocks, 256, SM_TOTAL>>>(in, W3, dinv, hs, M, 128);
    agg_kernel<<<agg_grid, 256>>>(ptr, csr, dinv, hs, b3, mask, in, pp, 0, 2);

    // pool reduce (no atomics)
    pool_reduce_kernel<<<BATCH * CDIM, 256>>>(pp, pool);

    // MLP head
    mlp_kernel<<<1, 256>>>(pool, lw1, lb1, lw2, lb2, lw3, lb3, lw4, lb4, out);
}

// round 13
// speedup vs baseline: 1.4098x; 1.0126x over previous
#include <cuda_runtime.h>
#include <cuda_fp16.h>
#include <mma.h>
#include <cstdint>

using namespace nvcuda;

#define NODES   68000
#define BATCH   4
#define NPROT   17000
#define CDIM    128
#define EMAX    2200000
#define PK      2125      // agg blocks per batch (2125*8 = 17000)
#define NLAYERS 3

#define SCAN_BLOCKS  64
#define SCAN_THREADS 256
#define SCAN_TOTAL   (SCAN_BLOCKS * SCAN_THREADS)
#define SCAN_CHUNK   ((NODES + SCAN_TOTAL - 1) / SCAN_TOTAL)

// ---------------- scratch (allocation-free: __device__ globals) ----------------
__device__ __align__(16) int    g_deg[NODES];
__device__ __align__(16) int    g_ptr[NODES + 1];
__device__ __align__(16) int    g_cursor[NODES];
__device__ __align__(16) int    g_csr[EMAX];
__device__ __align__(16) int    g_tpart[SCAN_TOTAL];
__device__ __align__(16) float  g_dinv[NODES];
__device__ __align__(16) __half g_xh[NODES * 256];     // fp16 copy of x
__device__ __align__(16) __half g_hs[NODES * CDIM];    // hs = dinv * (in @ W), fp16
__device__ __align__(16) __half g_in[NODES * CDIM];    // next-layer input (fp16)
__device__ __align__(16) float  g_ppart[NLAYERS * BATCH * CDIM * PK]; // pool partials
__device__ __align__(16) float  g_pooled[BATCH * CDIM];

// ---------------- fused: fp32->fp16 conversion of x + zero deg ----------------
__global__ void f2h_zero_kernel(const float* __restrict__ x, __half* __restrict__ xh,
                                int n4, int* __restrict__ deg, int n_deg) {
    int i = blockIdx.x * blockDim.x + threadIdx.x;
    int stride = gridDim.x * blockDim.x;
    for (int k = i; k < n_deg; k += stride) deg[k] = 0;
    for (int k = i; k < n4; k += stride) {
        float4 v = ((const float4*)x)[k];
        __half2 p0 = __floats2half2_rn(v.x, v.y);
        __half2 p1 = __floats2half2_rn(v.z, v.w);
        uint2 r;
        r.x = *(unsigned int*)&p0;
        r.y = *(unsigned int*)&p1;
        ((uint2*)xh)[k] = r;
    }
}

__global__ void deg_kernel(const int* __restrict__ dst, int* __restrict__ deg, int E) {
    int i = blockIdx.x * blockDim.x + threadIdx.x;
    if (i < E) atomicAdd(&deg[dst[i]], 1);
}

// ---------------- multi-block scan (phase 1 fused with dinv) -----------------
__global__ __launch_bounds__(SCAN_THREADS) void scan_p1_kernel(
    const int* __restrict__ deg, int* __restrict__ tpart, float* __restrict__ dinv)
{
    int t = blockIdx.x * blockDim.x + threadIdx.x;
    int lo = t * SCAN_CHUNK;
    int hi = lo + SCAN_CHUNK; if (hi > NODES) hi = NODES;
    int sum = 0;
    for (int i = lo; i < hi; i++) {
        int d = deg[i];
        sum += d;
        dinv[i] = rsqrtf((float)d + 1.0f);
    }
    tpart[t] = sum;
}

#define P2_T 1024
#define P2_PER (SCAN_TOTAL / P2_T)
__global__ __launch_bounds__(P2_T) void scan_p2_kernel(int* __restrict__ tpart)
{
    __shared__ int bs[P2_T];
    int t = threadIdx.x;
    int v[P2_PER];
    int local = 0;
#pragma unroll
    for (int i = 0; i < P2_PER; i++) {
        v[i] = tpart[t * P2_PER + i];
        local += v[i];
    }
    bs[t] = local;
    __syncthreads();
    for (int off = 1; off < P2_T; off <<= 1) {
        int x = 0;
        if (t >= off) x = bs[t - off];
        __syncthreads();
        if (t >= off) bs[t] += x;
        __syncthreads();
    }
    int run = (t == 0) ? 0 : bs[t - 1];
#pragma unroll
    for (int i = 0; i < P2_PER; i++) {
        tpart[t * P2_PER + i] = run;
        run += v[i];
    }
}

__global__ __launch_bounds__(SCAN_THREADS) void scan_p3_kernel(
    const int* __restrict__ deg, const int* __restrict__ tpart,
    int* __restrict__ ptr, int* __restrict__ cursor, int E)
{
    int t = blockIdx.x * blockDim.x + threadIdx.x;
    int lo = t * SCAN_CHUNK;
    int hi = lo + SCAN_CHUNK; if (hi > NODES) hi = NODES;
    int run = tpart[t];
    for (int i = lo; i < hi; i++) {
        ptr[i] = run;
        cursor[i] = run;
        run += deg[i];
    }
    if (t == 0) ptr[NODES] = E;
}

__global__ void build_csr_kernel(const int* __restrict__ src, const int* __restrict__ dst,
                                 int* __restrict__ cursor, int* __restrict__ csr, int E)
{
    int i = blockIdx.x * blockDim.x + threadIdx.x;
    if (i < E) {
        int d = dst[i];
        int pos = atomicAdd(&cursor[d], 1);
        csr[pos] = src[i];
    }
}

// ---------------- HGEMM (wmma): hs = fp16( dinv * (A @ W) ) ------------------
// A: [M,K] fp16; W: [K,128] fp32 (converted during B-tile smem fill).
#define GBM 128
#define GBK 32
#define LDA 40
#define LDB 136
#define LDC 132
#define SM_AS 0
#define SM_BS (GBM * LDA * 2)
#define SM_CS (SM_BS + GBK * LDB * 2)
#define SM_TOTAL (SM_CS + GBM * LDC * 4)

__global__ __launch_bounds__(256) void hgemm_kernel(
    const __half* __restrict__ A, const float* __restrict__ W,
    const float* __restrict__ dinv, __half* __restrict__ hs, int M, int K)
{
    extern __shared__ char smem[];
    __half* As = (__half*)(smem + SM_AS);
    __half* Bs = (__half*)(smem + SM_BS);
    float*  Cs = (float*)(smem + SM_CS);

    int tx = threadIdx.x;
    int row0 = blockIdx.x * GBM;
    int warp = tx >> 5;
    int wr = warp & 3;
    int wc = warp >> 2;

    wmma::fragment<wmma::accumulator, 16, 16, 16, float> acc[2][4];
#pragma unroll
    for (int mi = 0; mi < 2; mi++)
#pragma unroll
        for (int ni = 0; ni < 4; ni++) wmma::fill_fragment(acc[mi][ni], 0.f);

    for (int k0 = 0; k0 < K; k0 += GBK) {
        // ---- load A tile (fp16) ----
#pragma unroll
        for (int i = tx; i < GBM * GBK / 8; i += 256) {
            int r = i >> 2, c8 = (i & 3) * 8;
            int gr = row0 + r;
            float4 v = make_float4(0.f, 0.f, 0.f, 0.f);
            if (gr < M) v = *(const float4*)&A[(size_t)gr * K + k0 + c8];
            *(float4*)&As[r * LDA + c8] = v;
        }
        // ---- load B tile fp32 -> fp16 ----
#pragma unroll
        for (int i = tx; i < GBK * CDIM / 4; i += 256) {
            int r = i >> 5, c4 = (i & 31) * 4;
            float4 v = *(const float4*)&W[(size_t)(k0 + r) * CDIM + c4];
            __half2 p0 = __floats2half2_rn(v.x, v.y);
            __half2 p1 = __floats2half2_rn(v.z, v.w);
            uint2 w;
            w.x = *(unsigned int*)&p0;
            w.y = *(unsigned int*)&p1;
            *(uint2*)&Bs[r * LDB + c4] = w;
        }
        __syncthreads();
#pragma unroll
        for (int ks = 0; ks < GBK; ks += 16) {
            wmma::fragment<wmma::matrix_a, 16, 16, 16, __half, wmma::row_major> af[2];
            wmma::fragment<wmma::matrix_b, 16, 16, 16, __half, wmma::row_major> bf[4];
#pragma unroll
            for (int mi = 0; mi < 2; mi++)
                wmma::load_matrix_sync(af[mi], &As[(wr * 32 + mi * 16) * LDA + ks], LDA);
#pragma unroll
            for (int ni = 0; ni < 4; ni++)
                wmma::load_matrix_sync(bf[ni], &Bs[ks * LDB + wc * 64 + ni * 16], LDB);
#pragma unroll
            for (int mi = 0; mi < 2; mi++)
#pragma unroll
                for (int ni = 0; ni < 4; ni++)
                    wmma::mma_sync(acc[mi][ni], af[mi], bf[ni], acc[mi][ni]);
        }
        __syncthreads();
    }

#pragma unroll
    for (int mi = 0; mi < 2; mi++)
#pragma unroll
        for (int ni = 0; ni < 4; ni++)
            wmma::store_matrix_sync(&Cs[(wr * 32 + mi * 16) * LDC + wc * 64 + ni * 16],
                                    acc[mi][ni], LDC, wmma::mem_row_major);
    __syncthreads();

    int col4 = (tx & 31) * 4;
    int rstart = tx >> 5;
    for (int r = rstart; r < GBM; r += 8) {
        int gr = row0 + r;
        if (gr < M) {
            float dv = dinv[gr];
            float c0 = Cs[r * LDC + col4 + 0] * dv;
            float c1 = Cs[r * LDC + col4 + 1] * dv;
            float c2 = Cs[r * LDC + col4 + 2] * dv;
            float c3 = Cs[r * LDC + col4 + 3] * dv;
            __half2 p0 = __floats2half2_rn(c0, c1);
            __half2 p1 = __floats2half2_rn(c2, c3);
            uint2 w;
            w.x = *(unsigned int*)&p0;
            w.y = *(unsigned int*)&p1;
            *(uint2*)&hs[(size_t)gr * CDIM + col4] = w;
        }
    }
}

// ---------------- aggregation: warp per dst node, 2 rows per LDG -------------
// Half-warps: lanes 0-15 handle even edges, 16-31 odd edges; each lane loads
// uint4 (8 halves = 16B), so one warp LDG covers 2 full 256B rows.
__global__ __launch_bounds__(256) void agg_kernel(
    const int* __restrict__ ptr, const int* __restrict__ csr,
    const float* __restrict__ dinv, const __half* __restrict__ hs,
    const float* __restrict__ bias, const int* __restrict__ mask,
    __half* __restrict__ nxt, float* __restrict__ ppart,
    int write_nxt, int layer)
{
    __shared__ float pbuf[8][CDIM];
    int tx = threadIdx.x;
    int lane = tx & 31;
    int warp = tx >> 5;
    int hl = lane >> 4;          // half-warp index (0: even edges, 1: odd)
    int li = lane & 15;
    int co = li * 8;             // 8 halves (16B) per lane
    int b = blockIdx.y;
    int node = b * NPROT + blockIdx.x * 8 + warp;

    int beg = __ldg(&ptr[node]);
    int end = __ldg(&ptr[node + 1]);

    float a0 = 0.f, a1 = 0.f, a2 = 0.f, a3 = 0.f;
    float a4 = 0.f, a5 = 0.f, a6 = 0.f, a7 = 0.f;

#define ACC_ROW(R)  do {                                              \
        float2 f;                                                     \
        f = __half22float2(*(__half2*)&(R).x); a0 += f.x; a1 += f.y;  \
        f = __half22float2(((__half2*)&(R).x)[1]); a2 += f.x; a3 += f.y; \
        f = __half22float2(*(__half2*)&(R).z); a4 += f.x; a5 += f.y;  \
        f = __half22float2(((__half2*)&(R).z)[1]); a6 += f.x; a7 += f.y; \
    } while (0)

    // self term: only half 0 accumulates (counted once after combine)
    if (hl == 0) {
        uint4 r = *(const uint4*)(hs + (size_t)node * CDIM + co);
        ACC_ROW(r);
    }

    int e = beg;
    // 8 edges per iteration = 4 pair-loads per half-warp
    for (; e + 8 <= end; e += 8) {
        int i0 = __ldg(&csr[e + 0 + hl]);
        int i1 = __ldg(&csr[e + 2 + hl]);
        int i2 = __ldg(&csr[e + 4 + hl]);
        int i3 = __ldg(&csr[e + 6 + hl]);
        uint4 r0 = *(const uint4*)(hs + (size_t)i0 * CDIM + co);
        uint4 r1 = *(const uint4*)(hs + (size_t)i1 * CDIM + co);
        uint4 r2 = *(const uint4*)(hs + (size_t)i2 * CDIM + co);
        uint4 r3 = *(const uint4*)(hs + (size_t)i3 * CDIM + co);
        ACC_ROW(r0);
        ACC_ROW(r1);
        ACC_ROW(r2);
        ACC_ROW(r3);
    }
    // pair tail
    for (; e < end; e += 2) {
        if (e + hl < end) {
            int si = __ldg(&csr[e + hl]);
            uint4 r = *(const uint4*)(hs + (size_t)si * CDIM + co);
            ACC_ROW(r);
        }
    }
#undef ACC_ROW

    // combine the two half-warps (lane i += lane i+16)
    a0 += __shfl_down_sync(0xffffffffu, a0, 16);
    a1 += __shfl_down_sync(0xffffffffu, a1, 16);
    a2 += __shfl_down_sync(0xffffffffu, a2, 16);
    a3 += __shfl_down_sync(0xffffffffu, a3, 16);
    a4 += __shfl_down_sync(0xffffffffu, a4, 16);
    a5 += __shfl_down_sync(0xffffffffu, a5, 16);
    a6 += __shfl_down_sync(0xffffffffu, a6, 16);
    a7 += __shfl_down_sync(0xffffffffu, a7, 16);

    if (hl == 0) {
        float dv = dinv[node];
        float4 bA = *(const float4*)&bias[co];
        float4 bB = *(const float4*)&bias[co + 4];
        float r0 = fmaxf(a0 * dv + bA.x, 0.f);
        float r1 = fmaxf(a1 * dv + bA.y, 0.f);
        float r2 = fmaxf(a2 * dv + bA.z, 0.f);
        float r3 = fmaxf(a3 * dv + bA.w, 0.f);
        float r4 = fmaxf(a4 * dv + bB.x, 0.f);
        float r5 = fmaxf(a5 * dv + bB.y, 0.f);
        float r6 = fmaxf(a6 * dv + bB.z, 0.f);
        float r7 = fmaxf(a7 * dv + bB.w, 0.f);

        if (write_nxt) {
            __half2 p0 = __floats2half2_rn(r0, r1);
            __half2 p1 = __floats2half2_rn(r2, r3);
            __half2 p2 = __floats2half2_rn(r4, r5);
            __half2 p3 = __floats2half2_rn(r6, r7);
            uint4 w;
            w.x = *(unsigned int*)&p0;
            w.y = *(unsigned int*)&p1;
            w.z = *(unsigned int*)&p2;
            w.w = *(unsigned int*)&p3;
            *(uint4*)&nxt[(size_t)node * CDIM + co] = w;
        }

        float mf = __ldg(&mask[node]) ? 1.f : 0.f;
        float4 qa = make_float4(r0 * mf, r1 * mf, r2 * mf, r3 * mf);
        float4 qb = make_float4(r4 * mf, r5 * mf, r6 * mf, r7 * mf);
        *(float4*)&pbuf[warp][co] = qa;
        *(float4*)&pbuf[warp][co + 4] = qb;
    }
    __syncthreads();

    if (tx < CDIM) {
        float sum = 0.f;
#pragma unroll
        for (int w = 0; w < 8; w++) sum += pbuf[w][tx];
        ppart[(((size_t)layer * BATCH + b) * CDIM + tx) * PK + blockIdx.x] = sum;
    }
}

// ---------------- pool reduce ----------------
__global__ __launch_bounds__(256) void pool_reduce_kernel(
    const float* __restrict__ ppart, float* __restrict__ pooled)
{
    __shared__ float red[256];
    int bc = blockIdx.x;
    int tx = threadIdx.x;
    float sum = 0.f;
#pragma unroll
    for (int l = 0; l < NLAYERS; l++) {
        const float* row = ppart + (((size_t)l * BATCH) * CDIM + bc) * PK;
        for (int k = tx; k < PK; k += 256) sum += row[k];
    }
    red[tx] = sum;
    __syncthreads();
    for (int off = 128; off > 0; off >>= 1) {
        if (tx < off) red[tx] += red[tx + off];
        __syncthreads();
    }
    if (tx == 0) pooled[bc] = red[0];
}

// ---------------- tiny MLP ----------------
__global__ __launch_bounds__(256) void mlp_kernel(
    const float* __restrict__ pooled,
    const float* __restrict__ lw1, const float* __restrict__ lb1,
    const float* __restrict__ lw2, const float* __restrict__ lb2,
    const float* __restrict__ lw3, const float* __restrict__ lb3,
    const float* __restrict__ lw4, const float* __restrict__ lb4,
    float* __restrict__ out)
{
    __shared__ float sp[BATCH * 128];
    __shared__ float z1[BATCH * 256];
    __shared__ float z2[BATCH * 64];
    __shared__ float z3[BATCH * 16];
    int tx = threadIdx.x;

    for (int i = tx; i < BATCH * 128; i += 256) sp[i] = pooled[i];
    __syncthreads();

    for (int i = tx; i < BATCH * 256; i += 256) {
        int b = i >> 8, c = i & 255;
        float acc = lb1[c];
        for (int k = 0; k < 128; k++) acc += sp[b * 128 + k] * lw1[k * 256 + c];
        z1[i] = fmaxf(acc, 0.f);
    }
    __syncthreads();

    for (int i = tx; i < BATCH * 64; i += 256) {
        int b = i >> 6, c = i & 63;
        float acc = lb2[c];
        for (int k = 0; k < 256; k++) acc += z1[b * 256 + k] * lw2[k * 64 + c];
        z2[i] = fmaxf(acc, 0.f);
    }
    __syncthreads();

    if (tx < BATCH * 16) {
        int b = tx >> 4, c = tx & 15;
        float acc = lb3[c];
        for (int k = 0; k < 64; k++) acc += z2[b * 64 + k] * lw3[k * 16 + c];
        z3[tx] = fmaxf(acc, 0.f);
    }
    __syncthreads();

    if (tx < BATCH) {
        float acc = lb4[0];
        for (int k = 0; k < 16; k++) acc += z3[tx * 16 + k] * lw4[k];
        out[tx] = acc;
    }
}

// ---------------- launch ----------------
extern "C" void kernel_launch(void* const* d_in, const int* in_sizes, int n_in,
                              void* d_out, int out_size)
{
    const float* x    = (const float*)d_in[0];
    const int*   eidx = (const int*)d_in[1];
    const int*   mask = (const int*)d_in[2];
    const float* W1 = (const float*)d_in[3];  const float* b1 = (const float*)d_in[4];
    const float* W2 = (const float*)d_in[5];  const float* b2 = (const float*)d_in[6];
    const float* W3 = (const float*)d_in[7];  const float* b3 = (const float*)d_in[8];
    const float* lw1 = (const float*)d_in[9];  const float* lb1 = (const float*)d_in[10];
    const float* lw2 = (const float*)d_in[11]; const float* lb2 = (const float*)d_in[12];
    const float* lw3 = (const float*)d_in[13]; const float* lb3 = (const float*)d_in[14];
    const float* lw4 = (const float*)d_in[15]; const float* lb4 = (const float*)d_in[16];
    float* out = (float*)d_out;

    int M = NODES;
    int E = in_sizes[1] / 2;
    const int* src = eidx;
    const int* dst = eidx + E;

    void *p_deg, *p_ptr, *p_cur, *p_csr, *p_tp, *p_dinv, *p_xh, *p_hs, *p_in, *p_pp, *p_pool;
    cudaGetSymbolAddress(&p_deg, g_deg);
    cudaGetSymbolAddress(&p_ptr, g_ptr);
    cudaGetSymbolAddress(&p_cur, g_cursor);
    cudaGetSymbolAddress(&p_csr, g_csr);
    cudaGetSymbolAddress(&p_tp, g_tpart);
    cudaGetSymbolAddress(&p_dinv, g_dinv);
    cudaGetSymbolAddress(&p_xh, g_xh);
    cudaGetSymbolAddress(&p_hs, g_hs);
    cudaGetSymbolAddress(&p_in, g_in);
    cudaGetSymbolAddress(&p_pp, g_ppart);
    cudaGetSymbolAddress(&p_pool, g_pooled);
    int*    deg  = (int*)p_deg;
    int*    ptr  = (int*)p_ptr;
    int*    cur  = (int*)p_cur;
    int*    csr  = (int*)p_csr;
    int*    tp   = (int*)p_tp;
    float*  dinv = (float*)p_dinv;
    __half* xh   = (__half*)p_xh;
    __half* hs   = (__half*)p_hs;
    __half* in   = (__half*)p_in;
    float*  pp   = (float*)p_pp;
    float*  pool = (float*)p_pool;

    cudaFuncSetAttribute(hgemm_kernel, cudaFuncAttributeMaxDynamicSharedMemorySize, SM_TOTAL);

    dim3 agg_grid(PK, BATCH);
    int gemm_blocks = (M + GBM - 1) / GBM;

    // fused x conversion + deg zeroing
    f2h_zero_kernel<<<1024, 256>>>(x, xh, M * 256 / 4, deg, M);

    // degree count
    deg_kernel<<<(E + 255) / 256, 256>>>(dst, deg, E);

    // scan phase 1 fused with dinv
    scan_p1_kernel<<<SCAN_BLOCKS, SCAN_THREADS>>>(deg, tp, dinv);

    // layer-1 GEMM only needs xh + dinv — launch before the rest of the CSR chain
    hgemm_kernel<<<gemm_blocks, 256, SM_TOTAL>>>(xh, W1, dinv, hs, M, 256);

    scan_p2_kernel<<<1, P2_T>>>(tp);
    scan_p3_kernel<<<SCAN_BLOCKS, SCAN_THREADS>>>(deg, tp, ptr, cur, E);
    build_csr_kernel<<<(E + 255) / 256, 256>>>(src, dst, cur, csr, E);

    // layer 1 aggregation
    agg_kernel<<<agg_grid, 256>>>(ptr, csr, dinv, hs, b1, mask, in, pp, 1, 0);

    // layer 2
    hgemm_kernel<<<gemm_blocks, 256, SM_TOTAL>>>(in, W2, dinv, hs, M, 128);
    agg_kernel<<<agg_grid, 256>>>(ptr, csr, dinv, hs, b2, mask, in, pp, 1, 1);

    // layer 3 — no next-layer input needed
    hgemm_kernel<<<gemm_blocks, 256, SM_TOTAL>>>(in, W3, dinv, hs, M, 128);
    agg_kernel<<<agg_grid, 256>>>(ptr, csr, dinv, hs, b3, mask, in, pp, 0, 2);

    // pool reduce (no atomics)
    pool_reduce_kernel<<<BATCH * CDIM, 256>>>(pp, pool);

    // MLP head
    mlp_kernel<<<1, 256>>>(pool, lw1, lb1, lw2, lb2, lw3, lb3, lw4, lb4, out);
}